// round 14
// baseline (speedup 1.0000x reference)
#include <cuda_runtime.h>
#include <cstdint>

#define B_N   16384
#define K_N   2048
#define F_N   1024
#define H_N   1024
#define D_N   3
#define TOPK  8
#define NCAND 16
#define LN_EPS 1e-5f

// ---------------- scratch (static device globals; no runtime allocation) ---
__device__ float g_fn  [(size_t)B_N * F_N];   // normalized features (fp32, exact)
__device__ float g_gn  [(size_t)K_N * F_N];   // normalized graphone (fp32, exact)
__device__ float g_fnr [(size_t)B_N * F_N];   // tf32-rounded fn (for approx sim)
__device__ float g_gnr [(size_t)K_N * F_N];   // tf32-rounded gn
__device__ float g_sim [(size_t)B_N * K_N];   // APPROX similarity (1xTF32)
__device__ int   g_topk[(size_t)B_N * TOPK];  // top-8 prototype idx per row
__device__ float g_aggp[(size_t)B_N * F_N];   // max over top-8 graphone rows (tf32)
__device__ float g_x   [(size_t)B_N * F_N];   // depth-loop activations (tf32)
__device__ float g_am  [(size_t)B_N * F_N];   // max(aggp, x) (tf32)
__device__ float g_h   [(size_t)B_N * H_N];   // hidden
__device__ float g_wl  [(size_t)D_N * H_N * F_N];  // tf32-rounded weights
__device__ float g_wr  [(size_t)D_N * H_N * F_N];
__device__ float g_wp  [(size_t)D_N * F_N * H_N];

// ---------------- small PTX helpers ----------------------------------------
__device__ __forceinline__ float tf32r(float x) {
    float r;
    asm("cvt.rna.tf32.f32 %0, %1;" : "=f"(r) : "f"(x));
    return r;
}
__device__ __forceinline__ void ldsm4(uint32_t& r0, uint32_t& r1,
                                      uint32_t& r2, uint32_t& r3, uint32_t a) {
    asm volatile("ldmatrix.sync.aligned.m8n8.x4.shared.b16 {%0,%1,%2,%3}, [%4];"
                 : "=r"(r0), "=r"(r1), "=r"(r2), "=r"(r3) : "r"(a));
}
__device__ __forceinline__ void mma_tf32(float c[4],
                                         uint32_t a0, uint32_t a1, uint32_t a2, uint32_t a3,
                                         uint32_t b0, uint32_t b1) {
    asm volatile("mma.sync.aligned.m16n8k8.row.col.f32.tf32.tf32.f32 "
                 "{%0,%1,%2,%3},{%4,%5,%6,%7},{%8,%9},{%0,%1,%2,%3};"
                 : "+f"(c[0]), "+f"(c[1]), "+f"(c[2]), "+f"(c[3])
                 : "r"(a0), "r"(a1), "r"(a2), "r"(a3), "r"(b0), "r"(b1));
}
__device__ __forceinline__ void cpasync16(uint32_t dst, const void* src) {
    asm volatile("cp.async.cg.shared.global [%0], [%1], 16;" :: "r"(dst), "l"(src));
}
__device__ __forceinline__ void cp_commit() {
    asm volatile("cp.async.commit_group;");
}
__device__ __forceinline__ void cp_wait0() {
    asm volatile("cp.async.wait_group 0;");
}
__device__ __forceinline__ void cp_wait1() {
    asm volatile("cp.async.wait_group 1;");
}

// ---------------- row L2 normalize; writes exact + tf32-rounded copies -----
__global__ void normalize_rows(const float* __restrict__ feat,
                               const float* __restrict__ gr) {
    int row = blockIdx.x;
    const float* src;
    float* dst; float* dstr;
    if (row < B_N) {
        src = feat + (size_t)row * F_N;
        dst = g_fn + (size_t)row * F_N;  dstr = g_fnr + (size_t)row * F_N;
    } else {
        row -= B_N;
        src = gr + (size_t)row * F_N;
        dst = g_gn + (size_t)row * F_N;  dstr = g_gnr + (size_t)row * F_N;
    }
    int t = threadIdx.x;
    float4 v = ((const float4*)src)[t];
    float ss = v.x*v.x + v.y*v.y + v.z*v.z + v.w*v.w;
    __shared__ float red[8];
    #pragma unroll
    for (int o = 16; o > 0; o >>= 1) ss += __shfl_xor_sync(0xffffffffu, ss, o);
    if ((t & 31) == 0) red[t >> 5] = ss;
    __syncthreads();
    if (t == 0) {
        float s = 0.f;
        #pragma unroll
        for (int i = 0; i < 8; i++) s += red[i];
        red[0] = s;
    }
    __syncthreads();
    float inv = rsqrtf(red[0]);
    v.x *= inv; v.y *= inv; v.z *= inv; v.w *= inv;
    ((float4*)dst)[t] = v;
    float4 r4;
    r4.x = tf32r(v.x); r4.y = tf32r(v.y); r4.z = tf32r(v.z); r4.w = tf32r(v.w);
    ((float4*)dstr)[t] = r4;
}

// ---------------- TF32 tensor-core NT GEMM, 128x256 tile, BK=32, 3-stage ---
// Warp tile 64x64: 8 LDSM.x4 feed 32 MMAs per k-slice (2x better ratio than
// the 128x128 config); B smem traffic and barriers per FLOP halve.
// MODE 1: dual phase (Kd = 2F): k<F uses (A0,B0), k>=F uses (A1,B1), lda=F
// MODE 2: single (A0,B0)
// EPI 0: store raw   EPI 1: +bias,tf32,Am=max(aggp,x)   EPI 2: +bias -> out
template <int MODE, int EPI>
__global__ void __launch_bounds__(256, 1)
tgemm(const float* __restrict__ A0, const float* __restrict__ A1,
      const float* __restrict__ B0p, const float* __restrict__ B1p,
      const float* __restrict__ bias, const float* __restrict__ aggp,
      float* __restrict__ C, float* __restrict__ Am,
      int M, int N, int Kd) {
    const int BM = 128, BN = 256, BK = 32, NS = 3;
    const int STGA = BM * BK;                 // 4096 floats / stage
    const int STGB = BN * BK;                 // 8192 floats / stage
    extern __shared__ float smem[];
    float* As = smem;                         // NS*STGA floats (48 KB)
    float* Bs = smem + NS * STGA;             // NS*STGB floats (96 KB)

    const int tid  = threadIdx.x;
    const int lane = tid & 31;
    const int warp = tid >> 5;
    const int wm = warp >> 2;                 // 0..1  (64-row slabs)
    const int wn = warp & 3;                  // 0..3  (64-col slabs)
    const int g  = lane >> 3;
    const int li = lane & 7;
    const int m0 = blockIdx.y * BM;
    const int n0 = blockIdx.x * BN;

    const uint32_t sA = (uint32_t)__cvta_generic_to_shared(As);
    const uint32_t sB = (uint32_t)__cvta_generic_to_shared(Bs);

    float acc[4][8][4];
    #pragma unroll
    for (int a = 0; a < 4; a++)
        #pragma unroll
        for (int b = 0; b < 8; b++)
            #pragma unroll
            for (int c = 0; c < 4; c++) acc[a][b][c] = 0.f;

    const int halfK = Kd >> 1;
    const int NT = Kd / BK;

    // SW128 swizzle over 8 16B-chunks per 128B row: chunk' = c8 ^ (row & 7)
    auto issue_loads = [&](int kt) {
        int kk = kt * BK;
        int buf = kt % NS;
        const float* Aptr; const float* Bptr; int kb = kk; int ld;
        if (MODE == 1) {
            ld = halfK;
            if (kk >= halfK) { Aptr = A1; Bptr = B1p; kb = kk - halfK; }
            else             { Aptr = A0; Bptr = B0p; }
        } else {
            ld = Kd; Aptr = A0; Bptr = B0p;
        }
        #pragma unroll
        for (int it = 0; it < 4; it++) {      // A: 1024 float4
            int f = tid + it * 256;
            int r = f >> 3, c8 = f & 7;
            uint32_t soff = (uint32_t)(buf * STGA + r * BK + ((c8 ^ (r & 7)) << 2)) * 4u;
            cpasync16(sA + soff, Aptr + (size_t)(m0 + r) * ld + kb + c8 * 4);
        }
        #pragma unroll
        for (int it = 0; it < 8; it++) {      // B: 2048 float4
            int f = tid + it * 256;
            int r = f >> 3, c8 = f & 7;
            uint32_t soff = (uint32_t)(buf * STGB + r * BK + ((c8 ^ (r & 7)) << 2)) * 4u;
            cpasync16(sB + soff, Bptr + (size_t)(n0 + r) * ld + kb + c8 * 4);
        }
        cp_commit();
    };

    issue_loads(0);
    issue_loads(1);

    for (int kt = 0; kt < NT; kt++) {
        if (kt + 1 < NT) cp_wait1(); else cp_wait0();
        __syncthreads();
        if (kt + 2 < NT) issue_loads(kt + 2);

        const uint32_t baseA = sA + (uint32_t)((kt % NS) * STGA) * 4u;
        const uint32_t baseB = sB + (uint32_t)((kt % NS) * STGB) * 4u;

        #pragma unroll
        for (int s = 0; s < 4; s++) {         // 4 k=8 slices per BK=32
            uint32_t a[4][4];
            #pragma unroll
            for (int mi = 0; mi < 4; mi++) {
                int row = wm * 64 + mi * 16 + ((g & 1) << 3) + li;
                int ch  = (2 * s + (g >> 1)) ^ (row & 7);
                ldsm4(a[mi][0], a[mi][1], a[mi][2], a[mi][3],
                      baseA + (uint32_t)((row * BK + (ch << 2)) << 2));
            }
            uint32_t b[8][2];
            #pragma unroll
            for (int p = 0; p < 4; p++) {
                int row = wn * 64 + p * 16 + ((g >> 1) << 3) + li;
                int ch  = (2 * s + (g & 1)) ^ (row & 7);
                uint32_t r0, r1, r2, r3;
                ldsm4(r0, r1, r2, r3,
                      baseB + (uint32_t)((row * BK + (ch << 2)) << 2));
                b[2*p][0] = r0; b[2*p][1] = r1;
                b[2*p+1][0] = r2; b[2*p+1][1] = r3;
            }
            #pragma unroll
            for (int mi = 0; mi < 4; mi++)
                #pragma unroll
                for (int nj = 0; nj < 8; nj++)
                    mma_tf32(acc[mi][nj], a[mi][0], a[mi][1], a[mi][2], a[mi][3],
                             b[nj][0], b[nj][1]);
        }
    }

    #pragma unroll
    for (int mi = 0; mi < 4; mi++) {
        #pragma unroll
        for (int half = 0; half < 2; half++) {
            int row = m0 + wm * 64 + mi * 16 + (lane >> 2) + half * 8;
            #pragma unroll
            for (int nj = 0; nj < 8; nj++) {
                int col = n0 + wn * 64 + nj * 8 + ((lane & 3) << 1);
                float v0 = acc[mi][nj][half * 2 + 0];
                float v1 = acc[mi][nj][half * 2 + 1];
                size_t idx = (size_t)row * N + col;
                if (EPI >= 1) {
                    float2 bb = *(const float2*)(bias + col);
                    v0 += bb.x; v1 += bb.y;
                }
                if (EPI == 1) {
                    v0 = tf32r(v0); v1 = tf32r(v1);
                    float2 ag = *(const float2*)(aggp + idx);
                    float2 am;
                    am.x = fmaxf(ag.x, v0); am.y = fmaxf(ag.y, v1);
                    *(float2*)(Am + idx) = am;
                }
                float2 vv; vv.x = v0; vv.y = v1;
                *(float2*)(C + idx) = vv;
            }
        }
    }
}

// ---------------- warp-private topk (round-9/12 winner, unchanged) ----------
__global__ void __launch_bounds__(256)
topk_kernel(float* __restrict__ out, int write_assign) {
    extern __shared__ float svall[];          // 8 * 2048 floats = 64 KB
    int t = threadIdx.x;
    int lane = t & 31, w = t >> 5;
    int b = blockIdx.x * 8 + w;
    float* svw = svall + w * K_N;

    __shared__ int   cands[8][NCAND];
    __shared__ float exacts[8][NCAND];

    const float* row = g_sim + (size_t)b * K_N;
    float lmax = -3.0e38f; int lidx = 0;
    #pragma unroll
    for (int e = 0; e < 16; e++) {
        int q = lane + e * 32;
        float4 v = ((const float4*)row)[q];
        ((float4*)svw)[q] = v;
        int i0 = q * 4;
        if (v.x > lmax) { lmax = v.x; lidx = i0; }
        if (v.y > lmax) { lmax = v.y; lidx = i0 + 1; }
        if (v.z > lmax) { lmax = v.z; lidx = i0 + 2; }
        if (v.w > lmax) { lmax = v.w; lidx = i0 + 3; }
    }
    __syncwarp();

    for (int r = 0; r < NCAND; r++) {
        float bv = lmax; int bi = lidx;
        #pragma unroll
        for (int o = 16; o > 0; o >>= 1) {
            float ov = __shfl_xor_sync(0xffffffffu, bv, o);
            int   oi = __shfl_xor_sync(0xffffffffu, bi, o);
            if (ov > bv || (ov == bv && oi < bi)) { bv = ov; bi = oi; }
        }
        if (lane == 0) cands[w][r] = bi;
        if (((bi >> 2) & 31) == lane) {
            svw[bi] = -3.0e38f;
            lmax = -3.0e38f; lidx = 0;
            #pragma unroll
            for (int e = 0; e < 16; e++) {
                int q = lane + e * 32;
                float4 v = ((const float4*)svw)[q];
                int i0 = q * 4;
                if (v.x > lmax) { lmax = v.x; lidx = i0; }
                if (v.y > lmax) { lmax = v.y; lidx = i0 + 1; }
                if (v.z > lmax) { lmax = v.z; lidx = i0 + 2; }
                if (v.w > lmax) { lmax = v.w; lidx = i0 + 3; }
            }
        }
        __syncwarp();
    }

    const float* fp = g_fn + (size_t)b * F_N;
    for (int c = 0; c < NCAND; c++) {
        const float* gp = g_gn + (size_t)cands[w][c] * F_N;
        float s = 0.f;
        #pragma unroll
        for (int e = 0; e < F_N / 32; e++)
            s = fmaf(fp[e * 32 + lane], gp[e * 32 + lane], s);
        #pragma unroll
        for (int o = 16; o > 0; o >>= 1) s += __shfl_xor_sync(0xffffffffu, s, o);
        if (lane == 0) exacts[w][c] = s;
    }
    __syncwarp();

    if (lane == 0) {
        #pragma unroll
        for (int r = 0; r < TOPK; r++) {
            int bj = 0;
            float bvv = exacts[w][0];
            #pragma unroll
            for (int i = 1; i < NCAND; i++) {
                float vi = exacts[w][i];
                if (vi > bvv || (vi == bvv && cands[w][i] < cands[w][bj])) {
                    bvv = vi; bj = i;
                }
            }
            g_topk[b * TOPK + r] = cands[w][bj];
            if (r == 0 && write_assign) {
                #pragma unroll
                for (int dd = 0; dd < D_N; dd++)
                    out[(size_t)B_N * F_N + (size_t)dd * B_N + b] = (float)cands[w][bj];
            }
            exacts[w][bj] = -3.0e38f;
        }
    }
}

// ---------------- aggp (tf32), x0 = tf32(features), am0 = max(aggp,x0) -----
__global__ void aggproto_kernel(const float* __restrict__ graphone,
                                const float* __restrict__ features) {
    int b = blockIdx.x;
    int t = threadIdx.x;
    __shared__ int idx[TOPK];
    if (t < TOPK) idx[t] = g_topk[b * TOPK + t];
    __syncthreads();
    float4 m = ((const float4*)(graphone + (size_t)idx[0] * F_N))[t];
    #pragma unroll
    for (int j = 1; j < TOPK; j++) {
        float4 v = ((const float4*)(graphone + (size_t)idx[j] * F_N))[t];
        m.x = fmaxf(m.x, v.x); m.y = fmaxf(m.y, v.y);
        m.z = fmaxf(m.z, v.z); m.w = fmaxf(m.w, v.w);
    }
    m.x = tf32r(m.x); m.y = tf32r(m.y); m.z = tf32r(m.z); m.w = tf32r(m.w);
    ((float4*)(g_aggp + (size_t)b * F_N))[t] = m;
    float4 f = ((const float4*)(features + (size_t)b * F_N))[t];
    f.x = tf32r(f.x); f.y = tf32r(f.y); f.z = tf32r(f.z); f.w = tf32r(f.w);
    ((float4*)(g_x + (size_t)b * F_N))[t] = f;
    float4 a;
    a.x = fmaxf(m.x, f.x); a.y = fmaxf(m.y, f.y);
    a.z = fmaxf(m.z, f.z); a.w = fmaxf(m.w, f.w);
    ((float4*)(g_am + (size_t)b * F_N))[t] = a;
}

// ---------------- tf32 rounding copy: all three weight tensors, one launch --
__global__ void convert_tf32_all(const float* __restrict__ W_l,
                                 const float* __restrict__ W_r,
                                 const float* __restrict__ W_p, int n4) {
    int i = blockIdx.x * blockDim.x + threadIdx.x;
    if (i >= 3 * n4) return;
    const float* src; float* dst; int j;
    if (i < n4)            { src = W_l; dst = g_wl; j = i; }
    else if (i < 2 * n4)   { src = W_r; dst = g_wr; j = i - n4; }
    else                   { src = W_p; dst = g_wp; j = i - 2 * n4; }
    float4 v = ((const float4*)src)[j];
    v.x = tf32r(v.x); v.y = tf32r(v.y); v.z = tf32r(v.z); v.w = tf32r(v.w);
    ((float4*)dst)[j] = v;
}

// ---------------- LayerNorm + ReLU + tf32 round, in place on g_h -----------
__global__ void ln_relu_kernel(const float* __restrict__ gamma,
                               const float* __restrict__ beta) {
    int b = blockIdx.x;
    int t = threadIdx.x;
    float* row = g_h + (size_t)b * H_N;
    float4 v = ((float4*)row)[t];
    float s  = v.x + v.y + v.z + v.w;
    float ss = v.x*v.x + v.y*v.y + v.z*v.z + v.w*v.w;
    __shared__ float r1[8], r2[8];
    #pragma unroll
    for (int o = 16; o > 0; o >>= 1) {
        s  += __shfl_xor_sync(0xffffffffu, s,  o);
        ss += __shfl_xor_sync(0xffffffffu, ss, o);
    }
    if ((t & 31) == 0) { r1[t >> 5] = s; r2[t >> 5] = ss; }
    __syncthreads();
    if (t == 0) {
        float a = 0.f, c = 0.f;
        #pragma unroll
        for (int i = 0; i < 8; i++) { a += r1[i]; c += r2[i]; }
        r1[0] = a; r2[0] = c;
    }
    __syncthreads();
    float mu  = r1[0] * (1.0f / H_N);
    float var = r2[0] * (1.0f / H_N) - mu * mu;
    float inv = rsqrtf(var + LN_EPS);
    float4 gm = ((const float4*)gamma)[t];
    float4 be = ((const float4*)beta)[t];
    v.x = tf32r(fmaxf((v.x - mu) * inv * gm.x + be.x, 0.f));
    v.y = tf32r(fmaxf((v.y - mu) * inv * gm.y + be.y, 0.f));
    v.z = tf32r(fmaxf((v.z - mu) * inv * gm.z + be.z, 0.f));
    v.w = tf32r(fmaxf((v.w - mu) * inv * gm.w + be.w, 0.f));
    ((float4*)row)[t] = v;
}

// ---------------------------------------------------------------------------
extern "C" void kernel_launch(void* const* d_in, const int* in_sizes, int n_in,
                              void* d_out, int out_size) {
    const float* features = (const float*)d_in[0];
    const float* graphone = (const float*)d_in[1];
    const float* W_l      = (const float*)d_in[2];
    const float* W_r      = (const float*)d_in[3];
    const float* gamma    = (const float*)d_in[4];
    const float* beta     = (const float*)d_in[5];
    const float* W_p      = (const float*)d_in[6];
    const float* b_p      = (const float*)d_in[7];
    float* out = (float*)d_out;

    float *fnr, *gnr, *sim, *aggp, *x, *h, *am, *wl, *wr, *wp;
    cudaGetSymbolAddress((void**)&fnr,  g_fnr);
    cudaGetSymbolAddress((void**)&gnr,  g_gnr);
    cudaGetSymbolAddress((void**)&sim,  g_sim);
    cudaGetSymbolAddress((void**)&aggp, g_aggp);
    cudaGetSymbolAddress((void**)&x,    g_x);
    cudaGetSymbolAddress((void**)&h,    g_h);
    cudaGetSymbolAddress((void**)&am,   g_am);
    cudaGetSymbolAddress((void**)&wl,   g_wl);
    cudaGetSymbolAddress((void**)&wr,   g_wr);
    cudaGetSymbolAddress((void**)&wp,   g_wp);

    const int GEMM_SMEM = 3 * (128 + 256) * 32 * 4;   // 144 KB (3-stage, A+B)
    const int TOPK_SMEM = 8 * K_N * 4;                // 64 KB
    cudaFuncSetAttribute(tgemm<2, 0>, cudaFuncAttributeMaxDynamicSharedMemorySize, GEMM_SMEM);
    cudaFuncSetAttribute(tgemm<1, 0>, cudaFuncAttributeMaxDynamicSharedMemorySize, GEMM_SMEM);
    cudaFuncSetAttribute(tgemm<2, 1>, cudaFuncAttributeMaxDynamicSharedMemorySize, GEMM_SMEM);
    cudaFuncSetAttribute(tgemm<2, 2>, cudaFuncAttributeMaxDynamicSharedMemorySize, GEMM_SMEM);
    cudaFuncSetAttribute(topk_kernel, cudaFuncAttributeMaxDynamicSharedMemorySize, TOPK_SMEM);

    // 0) tf32-round all weights (single launch)
    int nW = D_N * H_N * F_N / 4;
    convert_tf32_all<<<(3 * nW + 255) / 256, 256>>>(W_l, W_r, W_p, nW);

    // 1) row normalization -> exact (rescore) + tf32-rounded (approx sim)
    normalize_rows<<<B_N + K_N, 256>>>(features, graphone);

    // 2) APPROX sim = fnr @ gnr^T  (TF32 TC GEMM, 128x256 tile)
    tgemm<2, 0><<<dim3(K_N / 256, B_N / 128), 256, GEMM_SMEM>>>(
        fnr, nullptr, gnr, nullptr, nullptr, nullptr, sim, nullptr,
        B_N, K_N, F_N);

    // 3) warp-private top-16 -> exact rescore -> top-8 (+ assignments)
    long long need = (long long)B_N * F_N + (long long)D_N * B_N;
    int write_assign = ((long long)out_size >= need) ? 1 : 0;
    topk_kernel<<<B_N / 8, 256, TOPK_SMEM>>>(out, write_assign);

    // 4) aggp (tf32), x0 = tf32(features), am0 = max(aggp, x0)
    aggproto_kernel<<<B_N, 256>>>(graphone, features);

    // 5) depth loop — tensor-core TF32 GEMMs (128x256 tiles)
    for (int d = 0; d < D_N; d++) {
        tgemm<1, 0><<<dim3(H_N / 256, B_N / 128), 256, GEMM_SMEM>>>(
            am, x,
            wl + (size_t)d * H_N * F_N, wr + (size_t)d * H_N * F_N,
            nullptr, nullptr, h, nullptr, B_N, H_N, 2 * F_N);

        ln_relu_kernel<<<B_N, 256>>>(gamma + (size_t)d * H_N,
                                     beta  + (size_t)d * H_N);

        if (d < D_N - 1) {
            tgemm<2, 1><<<dim3(F_N / 256, B_N / 128), 256, GEMM_SMEM>>>(
                h, nullptr, wp + (size_t)d * F_N * H_N, nullptr,
                b_p + (size_t)d * F_N, aggp, x, am, B_N, F_N, H_N);
        } else {
            tgemm<2, 2><<<dim3(F_N / 256, B_N / 128), 256, GEMM_SMEM>>>(
                h, nullptr, wp + (size_t)d * F_N * H_N, nullptr,
                b_p + (size_t)d * F_N, nullptr, out, nullptr, B_N, F_N, H_N);
        }
    }
}

// round 15
// speedup vs baseline: 1.1834x; 1.1834x over previous
#include <cuda_runtime.h>
#include <cstdint>

#define B_N   16384
#define K_N   2048
#define F_N   1024
#define H_N   1024
#define D_N   3
#define TOPK  8
#define NCAND 16
#define LN_EPS 1e-5f

// ---------------- scratch (static device globals; no runtime allocation) ---
__device__ float g_fn  [(size_t)B_N * F_N];   // normalized features (fp32, exact)
__device__ float g_gn  [(size_t)K_N * F_N];   // normalized graphone (fp32, exact)
__device__ float g_fnr [(size_t)B_N * F_N];   // tf32-rounded fn (for approx sim)
__device__ float g_gnr [(size_t)K_N * F_N];   // tf32-rounded gn
__device__ float g_sim [(size_t)B_N * K_N];   // APPROX similarity (1xTF32)
__device__ int   g_topk[(size_t)B_N * TOPK];  // top-8 prototype idx per row
__device__ float g_aggp[(size_t)B_N * F_N];   // max over top-8 graphone rows (tf32)
__device__ float g_x   [(size_t)B_N * F_N];   // depth-loop activations (tf32)
__device__ float g_am  [(size_t)B_N * F_N];   // max(aggp, x) (tf32)
__device__ float g_h   [(size_t)B_N * H_N];   // hidden
__device__ float g_wl  [(size_t)D_N * H_N * F_N];  // tf32-rounded weights
__device__ float g_wr  [(size_t)D_N * H_N * F_N];
__device__ float g_wp  [(size_t)D_N * F_N * H_N];

// ---------------- small PTX helpers ----------------------------------------
__device__ __forceinline__ float tf32r(float x) {
    float r;
    asm("cvt.rna.tf32.f32 %0, %1;" : "=f"(r) : "f"(x));
    return r;
}
__device__ __forceinline__ void ldsm4(uint32_t& r0, uint32_t& r1,
                                      uint32_t& r2, uint32_t& r3, uint32_t a) {
    asm volatile("ldmatrix.sync.aligned.m8n8.x4.shared.b16 {%0,%1,%2,%3}, [%4];"
                 : "=r"(r0), "=r"(r1), "=r"(r2), "=r"(r3) : "r"(a));
}
__device__ __forceinline__ void mma_tf32(float c[4],
                                         uint32_t a0, uint32_t a1, uint32_t a2, uint32_t a3,
                                         uint32_t b0, uint32_t b1) {
    asm volatile("mma.sync.aligned.m16n8k8.row.col.f32.tf32.tf32.f32 "
                 "{%0,%1,%2,%3},{%4,%5,%6,%7},{%8,%9},{%0,%1,%2,%3};"
                 : "+f"(c[0]), "+f"(c[1]), "+f"(c[2]), "+f"(c[3])
                 : "r"(a0), "r"(a1), "r"(a2), "r"(a3), "r"(b0), "r"(b1));
}
__device__ __forceinline__ void cpasync16(uint32_t dst, const void* src) {
    asm volatile("cp.async.cg.shared.global [%0], [%1], 16;" :: "r"(dst), "l"(src));
}
__device__ __forceinline__ void cp_commit() {
    asm volatile("cp.async.commit_group;");
}
__device__ __forceinline__ void cp_wait0() {
    asm volatile("cp.async.wait_group 0;");
}
__device__ __forceinline__ void cp_wait1() {
    asm volatile("cp.async.wait_group 1;");
}

// ---------------- row L2 normalize; writes exact + tf32-rounded copies -----
__global__ void normalize_rows(const float* __restrict__ feat,
                               const float* __restrict__ gr) {
    int row = blockIdx.x;
    const float* src;
    float* dst; float* dstr;
    if (row < B_N) {
        src = feat + (size_t)row * F_N;
        dst = g_fn + (size_t)row * F_N;  dstr = g_fnr + (size_t)row * F_N;
    } else {
        row -= B_N;
        src = gr + (size_t)row * F_N;
        dst = g_gn + (size_t)row * F_N;  dstr = g_gnr + (size_t)row * F_N;
    }
    int t = threadIdx.x;
    float4 v = ((const float4*)src)[t];
    float ss = v.x*v.x + v.y*v.y + v.z*v.z + v.w*v.w;
    __shared__ float red[8];
    #pragma unroll
    for (int o = 16; o > 0; o >>= 1) ss += __shfl_xor_sync(0xffffffffu, ss, o);
    if ((t & 31) == 0) red[t >> 5] = ss;
    __syncthreads();
    if (t == 0) {
        float s = 0.f;
        #pragma unroll
        for (int i = 0; i < 8; i++) s += red[i];
        red[0] = s;
    }
    __syncthreads();
    float inv = rsqrtf(red[0]);
    v.x *= inv; v.y *= inv; v.z *= inv; v.w *= inv;
    ((float4*)dst)[t] = v;
    float4 r4;
    r4.x = tf32r(v.x); r4.y = tf32r(v.y); r4.z = tf32r(v.z); r4.w = tf32r(v.w);
    ((float4*)dstr)[t] = r4;
}

// ---------------- TF32 tensor-core NT GEMM, 128x128, BK=32, 3-stage --------
// Compile-time NN (output cols) and KD (reduction length) so all addressing
// constant-folds. Round-12 winning configuration otherwise.
// MODE 1: dual phase (KD = 2F): k<F uses (A0,B0), k>=F uses (A1,B1), lda=F
// MODE 2: single (A0,B0)
// EPI 0: store raw   EPI 1: +bias,tf32,Am=max(aggp,x)   EPI 2: +bias -> out
template <int MODE, int EPI, int NN, int KD>
__global__ void __launch_bounds__(256, 2)
tgemm(const float* __restrict__ A0, const float* __restrict__ A1,
      const float* __restrict__ B0p, const float* __restrict__ B1p,
      const float* __restrict__ bias, const float* __restrict__ aggp,
      float* __restrict__ C, float* __restrict__ Am) {
    const int BM = 128, BK = 32, NS = 3;
    const int STG = BM * BK;                  // floats per operand per stage
    extern __shared__ float smem[];
    float* As = smem;                         // NS*STG floats (48 KB)
    float* Bs = smem + NS * STG;              // NS*STG floats (48 KB)

    const int tid  = threadIdx.x;
    const int lane = tid & 31;
    const int warp = tid >> 5;
    const int wm = warp >> 2;
    const int wn = warp & 3;
    const int g  = lane >> 3;
    const int li = lane & 7;
    const int m0 = blockIdx.y * BM;
    const int n0 = blockIdx.x * BM;

    const uint32_t sA = (uint32_t)__cvta_generic_to_shared(As);
    const uint32_t sB = (uint32_t)__cvta_generic_to_shared(Bs);

    float acc[4][4][4];
    #pragma unroll
    for (int a = 0; a < 4; a++)
        #pragma unroll
        for (int b = 0; b < 4; b++)
            #pragma unroll
            for (int c = 0; c < 4; c++) acc[a][b][c] = 0.f;

    const int halfK = KD >> 1;
    const int NT = KD / BK;

    // SW128 swizzle over 8 16B-chunks per 128B row: chunk' = c8 ^ (row & 7)
    auto issue_loads = [&](int kt) {
        int kk = kt * BK;
        int buf = kt % NS;
        const float* Aptr; const float* Bptr; int kb = kk;
        const int ld = (MODE == 1) ? halfK : KD;
        if (MODE == 1) {
            if (kk >= halfK) { Aptr = A1; Bptr = B1p; kb = kk - halfK; }
            else             { Aptr = A0; Bptr = B0p; }
        } else {
            Aptr = A0; Bptr = B0p;
        }
        #pragma unroll
        for (int it = 0; it < 4; it++) {      // 1024 float4 per operand
            int f = tid + it * 256;
            int r = f >> 3, c8 = f & 7;
            uint32_t soff = (uint32_t)(buf * STG + r * BK + ((c8 ^ (r & 7)) << 2)) * 4u;
            cpasync16(sA + soff, Aptr + (size_t)(m0 + r) * ld + kb + c8 * 4);
            cpasync16(sB + soff, Bptr + (size_t)(n0 + r) * ld + kb + c8 * 4);
        }
        cp_commit();
    };

    issue_loads(0);
    issue_loads(1);

    for (int kt = 0; kt < NT; kt++) {
        if (kt + 1 < NT) cp_wait1(); else cp_wait0();
        __syncthreads();
        if (kt + 2 < NT) issue_loads(kt + 2);

        const uint32_t baseA = sA + (uint32_t)((kt % NS) * STG) * 4u;
        const uint32_t baseB = sB + (uint32_t)((kt % NS) * STG) * 4u;

        #pragma unroll
        for (int s = 0; s < 4; s++) {         // 4 k=8 slices per BK=32
            uint32_t a[4][4];
            #pragma unroll
            for (int mi = 0; mi < 4; mi++) {
                int row = wm * 64 + mi * 16 + ((g & 1) << 3) + li;
                int ch  = (2 * s + (g >> 1)) ^ (row & 7);
                ldsm4(a[mi][0], a[mi][1], a[mi][2], a[mi][3],
                      baseA + (uint32_t)((row * BK + (ch << 2)) << 2));
            }
            uint32_t b[4][2];
            #pragma unroll
            for (int p = 0; p < 2; p++) {
                int row = wn * 32 + p * 16 + ((g >> 1) << 3) + li;
                int ch  = (2 * s + (g & 1)) ^ (row & 7);
                uint32_t r0, r1, r2, r3;
                ldsm4(r0, r1, r2, r3,
                      baseB + (uint32_t)((row * BK + (ch << 2)) << 2));
                b[2*p][0] = r0; b[2*p][1] = r1;
                b[2*p+1][0] = r2; b[2*p+1][1] = r3;
            }
            #pragma unroll
            for (int mi = 0; mi < 4; mi++)
                #pragma unroll
                for (int nj = 0; nj < 4; nj++)
                    mma_tf32(acc[mi][nj], a[mi][0], a[mi][1], a[mi][2], a[mi][3],
                             b[nj][0], b[nj][1]);
        }
    }

    #pragma unroll
    for (int mi = 0; mi < 4; mi++) {
        #pragma unroll
        for (int half = 0; half < 2; half++) {
            int row = m0 + wm * 64 + mi * 16 + (lane >> 2) + half * 8;
            #pragma unroll
            for (int nj = 0; nj < 4; nj++) {
                int col = n0 + wn * 32 + nj * 8 + ((lane & 3) << 1);
                float v0 = acc[mi][nj][half * 2 + 0];
                float v1 = acc[mi][nj][half * 2 + 1];
                size_t idx = (size_t)row * NN + col;
                if (EPI >= 1) {
                    float2 bb = *(const float2*)(bias + col);
                    v0 += bb.x; v1 += bb.y;
                }
                if (EPI == 1) {
                    v0 = tf32r(v0); v1 = tf32r(v1);
                    float2 ag = *(const float2*)(aggp + idx);
                    float2 am;
                    am.x = fmaxf(ag.x, v0); am.y = fmaxf(ag.y, v1);
                    *(float2*)(Am + idx) = am;
                }
                float2 vv; vv.x = v0; vv.y = v1;
                *(float2*)(C + idx) = vv;
            }
        }
    }
}

// ---------------- warp-private topk (round-9/12 winner, unchanged) ----------
__global__ void __launch_bounds__(256)
topk_kernel(float* __restrict__ out, int write_assign) {
    extern __shared__ float svall[];          // 8 * 2048 floats = 64 KB
    int t = threadIdx.x;
    int lane = t & 31, w = t >> 5;
    int b = blockIdx.x * 8 + w;
    float* svw = svall + w * K_N;

    __shared__ int   cands[8][NCAND];
    __shared__ float exacts[8][NCAND];

    const float* row = g_sim + (size_t)b * K_N;
    float lmax = -3.0e38f; int lidx = 0;
    #pragma unroll
    for (int e = 0; e < 16; e++) {
        int q = lane + e * 32;
        float4 v = ((const float4*)row)[q];
        ((float4*)svw)[q] = v;
        int i0 = q * 4;
        if (v.x > lmax) { lmax = v.x; lidx = i0; }
        if (v.y > lmax) { lmax = v.y; lidx = i0 + 1; }
        if (v.z > lmax) { lmax = v.z; lidx = i0 + 2; }
        if (v.w > lmax) { lmax = v.w; lidx = i0 + 3; }
    }
    __syncwarp();

    for (int r = 0; r < NCAND; r++) {
        float bv = lmax; int bi = lidx;
        #pragma unroll
        for (int o = 16; o > 0; o >>= 1) {
            float ov = __shfl_xor_sync(0xffffffffu, bv, o);
            int   oi = __shfl_xor_sync(0xffffffffu, bi, o);
            if (ov > bv || (ov == bv && oi < bi)) { bv = ov; bi = oi; }
        }
        if (lane == 0) cands[w][r] = bi;
        if (((bi >> 2) & 31) == lane) {
            svw[bi] = -3.0e38f;
            lmax = -3.0e38f; lidx = 0;
            #pragma unroll
            for (int e = 0; e < 16; e++) {
                int q = lane + e * 32;
                float4 v = ((const float4*)svw)[q];
                int i0 = q * 4;
                if (v.x > lmax) { lmax = v.x; lidx = i0; }
                if (v.y > lmax) { lmax = v.y; lidx = i0 + 1; }
                if (v.z > lmax) { lmax = v.z; lidx = i0 + 2; }
                if (v.w > lmax) { lmax = v.w; lidx = i0 + 3; }
            }
        }
        __syncwarp();
    }

    const float* fp = g_fn + (size_t)b * F_N;
    for (int c = 0; c < NCAND; c++) {
        const float* gp = g_gn + (size_t)cands[w][c] * F_N;
        float s = 0.f;
        #pragma unroll
        for (int e = 0; e < F_N / 32; e++)
            s = fmaf(fp[e * 32 + lane], gp[e * 32 + lane], s);
        #pragma unroll
        for (int o = 16; o > 0; o >>= 1) s += __shfl_xor_sync(0xffffffffu, s, o);
        if (lane == 0) exacts[w][c] = s;
    }
    __syncwarp();

    if (lane == 0) {
        #pragma unroll
        for (int r = 0; r < TOPK; r++) {
            int bj = 0;
            float bvv = exacts[w][0];
            #pragma unroll
            for (int i = 1; i < NCAND; i++) {
                float vi = exacts[w][i];
                if (vi > bvv || (vi == bvv && cands[w][i] < cands[w][bj])) {
                    bvv = vi; bj = i;
                }
            }
            g_topk[b * TOPK + r] = cands[w][bj];
            if (r == 0 && write_assign) {
                #pragma unroll
                for (int dd = 0; dd < D_N; dd++)
                    out[(size_t)B_N * F_N + (size_t)dd * B_N + b] = (float)cands[w][bj];
            }
            exacts[w][bj] = -3.0e38f;
        }
    }
}

// ---------------- aggp (tf32), x0 = tf32(features), am0 = max(aggp,x0) -----
__global__ void aggproto_kernel(const float* __restrict__ graphone,
                                const float* __restrict__ features) {
    int b = blockIdx.x;
    int t = threadIdx.x;
    __shared__ int idx[TOPK];
    if (t < TOPK) idx[t] = g_topk[b * TOPK + t];
    __syncthreads();
    float4 m = ((const float4*)(graphone + (size_t)idx[0] * F_N))[t];
    #pragma unroll
    for (int j = 1; j < TOPK; j++) {
        float4 v = ((const float4*)(graphone + (size_t)idx[j] * F_N))[t];
        m.x = fmaxf(m.x, v.x); m.y = fmaxf(m.y, v.y);
        m.z = fmaxf(m.z, v.z); m.w = fmaxf(m.w, v.w);
    }
    m.x = tf32r(m.x); m.y = tf32r(m.y); m.z = tf32r(m.z); m.w = tf32r(m.w);
    ((float4*)(g_aggp + (size_t)b * F_N))[t] = m;
    float4 f = ((const float4*)(features + (size_t)b * F_N))[t];
    f.x = tf32r(f.x); f.y = tf32r(f.y); f.z = tf32r(f.z); f.w = tf32r(f.w);
    ((float4*)(g_x + (size_t)b * F_N))[t] = f;
    float4 a;
    a.x = fmaxf(m.x, f.x); a.y = fmaxf(m.y, f.y);
    a.z = fmaxf(m.z, f.z); a.w = fmaxf(m.w, f.w);
    ((float4*)(g_am + (size_t)b * F_N))[t] = a;
}

// ---------------- tf32 rounding copy: all three weight tensors, one launch --
__global__ void convert_tf32_all(const float* __restrict__ W_l,
                                 const float* __restrict__ W_r,
                                 const float* __restrict__ W_p, int n4) {
    int i = blockIdx.x * blockDim.x + threadIdx.x;
    if (i >= 3 * n4) return;
    const float* src; float* dst; int j;
    if (i < n4)            { src = W_l; dst = g_wl; j = i; }
    else if (i < 2 * n4)   { src = W_r; dst = g_wr; j = i - n4; }
    else                   { src = W_p; dst = g_wp; j = i - 2 * n4; }
    float4 v = ((const float4*)src)[j];
    v.x = tf32r(v.x); v.y = tf32r(v.y); v.z = tf32r(v.z); v.w = tf32r(v.w);
    ((float4*)dst)[j] = v;
}

// ---------------- LayerNorm + ReLU + tf32 round, in place on g_h -----------
__global__ void ln_relu_kernel(const float* __restrict__ gamma,
                               const float* __restrict__ beta) {
    int b = blockIdx.x;
    int t = threadIdx.x;
    float* row = g_h + (size_t)b * H_N;
    float4 v = ((float4*)row)[t];
    float s  = v.x + v.y + v.z + v.w;
    float ss = v.x*v.x + v.y*v.y + v.z*v.z + v.w*v.w;
    __shared__ float r1[8], r2[8];
    #pragma unroll
    for (int o = 16; o > 0; o >>= 1) {
        s  += __shfl_xor_sync(0xffffffffu, s,  o);
        ss += __shfl_xor_sync(0xffffffffu, ss, o);
    }
    if ((t & 31) == 0) { r1[t >> 5] = s; r2[t >> 5] = ss; }
    __syncthreads();
    if (t == 0) {
        float a = 0.f, c = 0.f;
        #pragma unroll
        for (int i = 0; i < 8; i++) { a += r1[i]; c += r2[i]; }
        r1[0] = a; r2[0] = c;
    }
    __syncthreads();
    float mu  = r1[0] * (1.0f / H_N);
    float var = r2[0] * (1.0f / H_N) - mu * mu;
    float inv = rsqrtf(var + LN_EPS);
    float4 gm = ((const float4*)gamma)[t];
    float4 be = ((const float4*)beta)[t];
    v.x = tf32r(fmaxf((v.x - mu) * inv * gm.x + be.x, 0.f));
    v.y = tf32r(fmaxf((v.y - mu) * inv * gm.y + be.y, 0.f));
    v.z = tf32r(fmaxf((v.z - mu) * inv * gm.z + be.z, 0.f));
    v.w = tf32r(fmaxf((v.w - mu) * inv * gm.w + be.w, 0.f));
    ((float4*)row)[t] = v;
}

// ---------------------------------------------------------------------------
extern "C" void kernel_launch(void* const* d_in, const int* in_sizes, int n_in,
                              void* d_out, int out_size) {
    const float* features = (const float*)d_in[0];
    const float* graphone = (const float*)d_in[1];
    const float* W_l      = (const float*)d_in[2];
    const float* W_r      = (const float*)d_in[3];
    const float* gamma    = (const float*)d_in[4];
    const float* beta     = (const float*)d_in[5];
    const float* W_p      = (const float*)d_in[6];
    const float* b_p      = (const float*)d_in[7];
    float* out = (float*)d_out;

    float *fnr, *gnr, *sim, *aggp, *x, *h, *am, *wl, *wr, *wp;
    cudaGetSymbolAddress((void**)&fnr,  g_fnr);
    cudaGetSymbolAddress((void**)&gnr,  g_gnr);
    cudaGetSymbolAddress((void**)&sim,  g_sim);
    cudaGetSymbolAddress((void**)&aggp, g_aggp);
    cudaGetSymbolAddress((void**)&x,    g_x);
    cudaGetSymbolAddress((void**)&h,    g_h);
    cudaGetSymbolAddress((void**)&am,   g_am);
    cudaGetSymbolAddress((void**)&wl,   g_wl);
    cudaGetSymbolAddress((void**)&wr,   g_wr);
    cudaGetSymbolAddress((void**)&wp,   g_wp);

    const int GEMM_SMEM = 3 * 128 * 32 * 4 * 2;   // 96 KB (3-stage, A+B)
    const int TOPK_SMEM = 8 * K_N * 4;            // 64 KB
    cudaFuncSetAttribute((const void*)tgemm<2, 0, K_N, F_N>,
                         cudaFuncAttributeMaxDynamicSharedMemorySize, GEMM_SMEM);
    cudaFuncSetAttribute((const void*)tgemm<1, 0, H_N, 2 * F_N>,
                         cudaFuncAttributeMaxDynamicSharedMemorySize, GEMM_SMEM);
    cudaFuncSetAttribute((const void*)tgemm<2, 1, F_N, H_N>,
                         cudaFuncAttributeMaxDynamicSharedMemorySize, GEMM_SMEM);
    cudaFuncSetAttribute((const void*)tgemm<2, 2, F_N, H_N>,
                         cudaFuncAttributeMaxDynamicSharedMemorySize, GEMM_SMEM);
    cudaFuncSetAttribute(topk_kernel, cudaFuncAttributeMaxDynamicSharedMemorySize, TOPK_SMEM);

    // 0) tf32-round all weights (single launch)
    int nW = D_N * H_N * F_N / 4;
    convert_tf32_all<<<(3 * nW + 255) / 256, 256>>>(W_l, W_r, W_p, nW);

    // 1) row normalization -> exact (rescore) + tf32-rounded (approx sim)
    normalize_rows<<<B_N + K_N, 256>>>(features, graphone);

    // 2) APPROX sim = fnr @ gnr^T  (TF32 TC GEMM, 128x128 tile)
    tgemm<2, 0, K_N, F_N><<<dim3(K_N / 128, B_N / 128), 256, GEMM_SMEM>>>(
        fnr, nullptr, gnr, nullptr, nullptr, nullptr, sim, nullptr);

    // 3) warp-private top-16 -> exact rescore -> top-8 (+ assignments)
    long long need = (long long)B_N * F_N + (long long)D_N * B_N;
    int write_assign = ((long long)out_size >= need) ? 1 : 0;
    topk_kernel<<<B_N / 8, 256, TOPK_SMEM>>>(out, write_assign);

    // 4) aggp (tf32), x0 = tf32(features), am0 = max(aggp, x0)
    aggproto_kernel<<<B_N, 256>>>(graphone, features);

    // 5) depth loop — tensor-core TF32 GEMMs
    for (int d = 0; d < D_N; d++) {
        tgemm<1, 0, H_N, 2 * F_N><<<dim3(H_N / 128, B_N / 128), 256, GEMM_SMEM>>>(
            am, x,
            wl + (size_t)d * H_N * F_N, wr + (size_t)d * H_N * F_N,
            nullptr, nullptr, h, nullptr);

        ln_relu_kernel<<<B_N, 256>>>(gamma + (size_t)d * H_N,
                                     beta  + (size_t)d * H_N);

        if (d < D_N - 1) {
            tgemm<2, 1, F_N, H_N><<<dim3(F_N / 128, B_N / 128), 256, GEMM_SMEM>>>(
                h, nullptr, wp + (size_t)d * F_N * H_N, nullptr,
                b_p + (size_t)d * F_N, aggp, x, am);
        } else {
            tgemm<2, 2, F_N, H_N><<<dim3(F_N / 128, B_N / 128), 256, GEMM_SMEM>>>(
                h, nullptr, wp + (size_t)d * F_N * H_N, nullptr,
                b_p + (size_t)d * F_N, nullptr, out, nullptr);
        }
    }
}

// round 16
// speedup vs baseline: 1.1934x; 1.0085x over previous
#include <cuda_runtime.h>
#include <cstdint>

#define B_N   16384
#define K_N   2048
#define F_N   1024
#define H_N   1024
#define D_N   3
#define TOPK  8
#define NCAND 16
#define LN_EPS 1e-5f

// ---------------- scratch (static device globals; no runtime allocation) ---
__device__ float g_fn  [(size_t)B_N * F_N];   // normalized features (fp32, exact)
__device__ float g_gn  [(size_t)K_N * F_N];   // normalized graphone (fp32, exact)
__device__ float g_fnr [(size_t)B_N * F_N];   // tf32-rounded fn (for approx sim)
__device__ float g_gnr [(size_t)K_N * F_N];   // tf32-rounded gn
__device__ float g_sim [(size_t)B_N * K_N];   // APPROX similarity (1xTF32)
__device__ int   g_topk[(size_t)B_N * TOPK];  // top-8 prototype idx per row
__device__ float g_aggp[(size_t)B_N * F_N];   // max over top-8 graphone rows (tf32)
__device__ float g_x   [(size_t)B_N * F_N];   // depth-loop activations (tf32)
__device__ float g_am  [(size_t)B_N * F_N];   // max(aggp, x) (tf32)
__device__ float g_h   [(size_t)B_N * H_N];   // hidden
__device__ float g_wl  [(size_t)D_N * H_N * F_N];  // tf32-rounded weights
__device__ float g_wr  [(size_t)D_N * H_N * F_N];
__device__ float g_wp  [(size_t)D_N * F_N * H_N];

// ---------------- small PTX helpers ----------------------------------------
__device__ __forceinline__ float tf32r(float x) {
    float r;
    asm("cvt.rna.tf32.f32 %0, %1;" : "=f"(r) : "f"(x));
    return r;
}
__device__ __forceinline__ void ldsm4(uint32_t& r0, uint32_t& r1,
                                      uint32_t& r2, uint32_t& r3, uint32_t a) {
    asm volatile("ldmatrix.sync.aligned.m8n8.x4.shared.b16 {%0,%1,%2,%3}, [%4];"
                 : "=r"(r0), "=r"(r1), "=r"(r2), "=r"(r3) : "r"(a));
}
__device__ __forceinline__ void mma_tf32(float c[4],
                                         uint32_t a0, uint32_t a1, uint32_t a2, uint32_t a3,
                                         uint32_t b0, uint32_t b1) {
    asm volatile("mma.sync.aligned.m16n8k8.row.col.f32.tf32.tf32.f32 "
                 "{%0,%1,%2,%3},{%4,%5,%6,%7},{%8,%9},{%0,%1,%2,%3};"
                 : "+f"(c[0]), "+f"(c[1]), "+f"(c[2]), "+f"(c[3])
                 : "r"(a0), "r"(a1), "r"(a2), "r"(a3), "r"(b0), "r"(b1));
}
__device__ __forceinline__ void cpasync16(uint32_t dst, const void* src) {
    asm volatile("cp.async.cg.shared.global [%0], [%1], 16;" :: "r"(dst), "l"(src));
}
__device__ __forceinline__ void cp_commit() {
    asm volatile("cp.async.commit_group;");
}
__device__ __forceinline__ void cp_wait0() {
    asm volatile("cp.async.wait_group 0;");
}
__device__ __forceinline__ void cp_wait1() {
    asm volatile("cp.async.wait_group 1;");
}

// ---------------- fused prep: row L2 normalize + weight tf32 rounding ------
// Blocks [0, B_N+K_N): normalize one row (exact + tf32-rounded copies).
// Blocks [B_N+K_N, B_N+K_N+NCONV): tf32-round the three weight tensors.
#define NPREP (B_N + K_N)
#define NW4   (D_N * H_N * F_N / 4)              // float4s per weight tensor
#define NCONV ((3 * NW4 + 255) / 256)

__global__ void prep_kernel(const float* __restrict__ feat,
                            const float* __restrict__ gr,
                            const float* __restrict__ W_l,
                            const float* __restrict__ W_r,
                            const float* __restrict__ W_p) {
    int blk = blockIdx.x;
    int t = threadIdx.x;
    if (blk >= NPREP) {
        // ---- weight conversion part ----------------------------------------
        int i = (blk - NPREP) * 256 + t;
        if (i >= 3 * NW4) return;
        const float* src; float* dst; int j;
        if (i < NW4)            { src = W_l; dst = g_wl; j = i; }
        else if (i < 2 * NW4)   { src = W_r; dst = g_wr; j = i - NW4; }
        else                    { src = W_p; dst = g_wp; j = i - 2 * NW4; }
        float4 v = ((const float4*)src)[j];
        v.x = tf32r(v.x); v.y = tf32r(v.y); v.z = tf32r(v.z); v.w = tf32r(v.w);
        ((float4*)dst)[j] = v;
        return;
    }
    // ---- row normalization part --------------------------------------------
    int row = blk;
    const float* src;
    float* dst; float* dstr;
    if (row < B_N) {
        src = feat + (size_t)row * F_N;
        dst = g_fn + (size_t)row * F_N;  dstr = g_fnr + (size_t)row * F_N;
    } else {
        row -= B_N;
        src = gr + (size_t)row * F_N;
        dst = g_gn + (size_t)row * F_N;  dstr = g_gnr + (size_t)row * F_N;
    }
    float4 v = ((const float4*)src)[t];
    float ss = v.x*v.x + v.y*v.y + v.z*v.z + v.w*v.w;
    __shared__ float red[8];
    #pragma unroll
    for (int o = 16; o > 0; o >>= 1) ss += __shfl_xor_sync(0xffffffffu, ss, o);
    if ((t & 31) == 0) red[t >> 5] = ss;
    __syncthreads();
    if (t == 0) {
        float s = 0.f;
        #pragma unroll
        for (int i = 0; i < 8; i++) s += red[i];
        red[0] = s;
    }
    __syncthreads();
    float inv = rsqrtf(red[0]);
    v.x *= inv; v.y *= inv; v.z *= inv; v.w *= inv;
    ((float4*)dst)[t] = v;
    float4 r4;
    r4.x = tf32r(v.x); r4.y = tf32r(v.y); r4.z = tf32r(v.z); r4.w = tf32r(v.w);
    ((float4*)dstr)[t] = r4;
}

// ---------------- TF32 tensor-core NT GEMM, BK=32, 3-stage, dyn smem -------
// (round-12 winner, byte-identical numerics)
// MODE 1: dual phase (Kd = 2F): k<F uses (A0,B0), k>=F uses (A1,B1), lda=F
// MODE 2: single (A0,B0)
// EPI 0: store raw   EPI 1: +bias,tf32,Am=max(aggp,x)   EPI 2: +bias -> out
template <int MODE, int EPI>
__global__ void __launch_bounds__(256, 2)
tgemm(const float* __restrict__ A0, const float* __restrict__ A1,
      const float* __restrict__ B0p, const float* __restrict__ B1p,
      const float* __restrict__ bias, const float* __restrict__ aggp,
      float* __restrict__ C, float* __restrict__ Am,
      int M, int N, int Kd) {
    const int BM = 128, BK = 32, NS = 3;
    const int STG = BM * BK;                  // floats per operand per stage
    extern __shared__ float smem[];
    float* As = smem;                         // NS*STG floats (48 KB)
    float* Bs = smem + NS * STG;              // NS*STG floats (48 KB)

    const int tid  = threadIdx.x;
    const int lane = tid & 31;
    const int warp = tid >> 5;
    const int wm = warp >> 2;
    const int wn = warp & 3;
    const int g  = lane >> 3;
    const int li = lane & 7;
    const int m0 = blockIdx.y * BM;
    const int n0 = blockIdx.x * BM;

    const uint32_t sA = (uint32_t)__cvta_generic_to_shared(As);
    const uint32_t sB = (uint32_t)__cvta_generic_to_shared(Bs);

    float acc[4][4][4];
    #pragma unroll
    for (int a = 0; a < 4; a++)
        #pragma unroll
        for (int b = 0; b < 4; b++)
            #pragma unroll
            for (int c = 0; c < 4; c++) acc[a][b][c] = 0.f;

    const int halfK = Kd >> 1;
    const int NT = Kd / BK;

    // SW128 swizzle over 8 16B-chunks per 128B row: chunk' = c8 ^ (row & 7)
    auto issue_loads = [&](int kt) {
        int kk = kt * BK;
        int buf = kt % NS;
        const float* Aptr; const float* Bptr; int kb = kk; int ld;
        if (MODE == 1) {
            ld = halfK;
            if (kk >= halfK) { Aptr = A1; Bptr = B1p; kb = kk - halfK; }
            else             { Aptr = A0; Bptr = B0p; }
        } else {
            ld = Kd; Aptr = A0; Bptr = B0p;
        }
        #pragma unroll
        for (int it = 0; it < 4; it++) {      // 1024 float4 per operand
            int f = tid + it * 256;
            int r = f >> 3, c8 = f & 7;
            uint32_t soff = (uint32_t)(buf * STG + r * BK + ((c8 ^ (r & 7)) << 2)) * 4u;
            cpasync16(sA + soff, Aptr + (size_t)(m0 + r) * ld + kb + c8 * 4);
            cpasync16(sB + soff, Bptr + (size_t)(n0 + r) * ld + kb + c8 * 4);
        }
        cp_commit();
    };

    issue_loads(0);
    issue_loads(1);

    for (int kt = 0; kt < NT; kt++) {
        if (kt + 1 < NT) cp_wait1(); else cp_wait0();
        __syncthreads();
        if (kt + 2 < NT) issue_loads(kt + 2);

        const uint32_t baseA = sA + (uint32_t)((kt % NS) * STG) * 4u;
        const uint32_t baseB = sB + (uint32_t)((kt % NS) * STG) * 4u;

        #pragma unroll
        for (int s = 0; s < 4; s++) {         // 4 k=8 slices per BK=32
            uint32_t a[4][4];
            #pragma unroll
            for (int mi = 0; mi < 4; mi++) {
                int row = wm * 64 + mi * 16 + ((g & 1) << 3) + li;
                int ch  = (2 * s + (g >> 1)) ^ (row & 7);
                ldsm4(a[mi][0], a[mi][1], a[mi][2], a[mi][3],
                      baseA + (uint32_t)((row * BK + (ch << 2)) << 2));
            }
            uint32_t b[4][2];
            #pragma unroll
            for (int p = 0; p < 2; p++) {
                int row = wn * 32 + p * 16 + ((g >> 1) << 3) + li;
                int ch  = (2 * s + (g & 1)) ^ (row & 7);
                uint32_t r0, r1, r2, r3;
                ldsm4(r0, r1, r2, r3,
                      baseB + (uint32_t)((row * BK + (ch << 2)) << 2));
                b[2*p][0] = r0; b[2*p][1] = r1;
                b[2*p+1][0] = r2; b[2*p+1][1] = r3;
            }
            #pragma unroll
            for (int mi = 0; mi < 4; mi++)
                #pragma unroll
                for (int nj = 0; nj < 4; nj++)
                    mma_tf32(acc[mi][nj], a[mi][0], a[mi][1], a[mi][2], a[mi][3],
                             b[nj][0], b[nj][1]);
        }
    }

    #pragma unroll
    for (int mi = 0; mi < 4; mi++) {
        #pragma unroll
        for (int half = 0; half < 2; half++) {
            int row = m0 + wm * 64 + mi * 16 + (lane >> 2) + half * 8;
            #pragma unroll
            for (int nj = 0; nj < 4; nj++) {
                int col = n0 + wn * 32 + nj * 8 + ((lane & 3) << 1);
                float v0 = acc[mi][nj][half * 2 + 0];
                float v1 = acc[mi][nj][half * 2 + 1];
                size_t idx = (size_t)row * N + col;
                if (EPI >= 1) {
                    float2 bb = *(const float2*)(bias + col);
                    v0 += bb.x; v1 += bb.y;
                }
                if (EPI == 1) {
                    v0 = tf32r(v0); v1 = tf32r(v1);
                    float2 ag = *(const float2*)(aggp + idx);
                    float2 am;
                    am.x = fmaxf(ag.x, v0); am.y = fmaxf(ag.y, v1);
                    *(float2*)(Am + idx) = am;
                }
                float2 vv; vv.x = v0; vv.y = v1;
                *(float2*)(C + idx) = vv;
            }
        }
    }
}

// ---------------- warp-private topk (round-9/12 winner, unchanged) ----------
__global__ void __launch_bounds__(256)
topk_kernel(float* __restrict__ out, int write_assign) {
    extern __shared__ float svall[];          // 8 * 2048 floats = 64 KB
    int t = threadIdx.x;
    int lane = t & 31, w = t >> 5;
    int b = blockIdx.x * 8 + w;
    float* svw = svall + w * K_N;

    __shared__ int   cands[8][NCAND];
    __shared__ float exacts[8][NCAND];

    const float* row = g_sim + (size_t)b * K_N;
    float lmax = -3.0e38f; int lidx = 0;
    #pragma unroll
    for (int e = 0; e < 16; e++) {
        int q = lane + e * 32;
        float4 v = ((const float4*)row)[q];
        ((float4*)svw)[q] = v;
        int i0 = q * 4;
        if (v.x > lmax) { lmax = v.x; lidx = i0; }
        if (v.y > lmax) { lmax = v.y; lidx = i0 + 1; }
        if (v.z > lmax) { lmax = v.z; lidx = i0 + 2; }
        if (v.w > lmax) { lmax = v.w; lidx = i0 + 3; }
    }
    __syncwarp();

    for (int r = 0; r < NCAND; r++) {
        float bv = lmax; int bi = lidx;
        #pragma unroll
        for (int o = 16; o > 0; o >>= 1) {
            float ov = __shfl_xor_sync(0xffffffffu, bv, o);
            int   oi = __shfl_xor_sync(0xffffffffu, bi, o);
            if (ov > bv || (ov == bv && oi < bi)) { bv = ov; bi = oi; }
        }
        if (lane == 0) cands[w][r] = bi;
        if (((bi >> 2) & 31) == lane) {
            svw[bi] = -3.0e38f;
            lmax = -3.0e38f; lidx = 0;
            #pragma unroll
            for (int e = 0; e < 16; e++) {
                int q = lane + e * 32;
                float4 v = ((const float4*)svw)[q];
                int i0 = q * 4;
                if (v.x > lmax) { lmax = v.x; lidx = i0; }
                if (v.y > lmax) { lmax = v.y; lidx = i0 + 1; }
                if (v.z > lmax) { lmax = v.z; lidx = i0 + 2; }
                if (v.w > lmax) { lmax = v.w; lidx = i0 + 3; }
            }
        }
        __syncwarp();
    }

    const float* fp = g_fn + (size_t)b * F_N;
    for (int c = 0; c < NCAND; c++) {
        const float* gp = g_gn + (size_t)cands[w][c] * F_N;
        float s = 0.f;
        #pragma unroll
        for (int e = 0; e < F_N / 32; e++)
            s = fmaf(fp[e * 32 + lane], gp[e * 32 + lane], s);
        #pragma unroll
        for (int o = 16; o > 0; o >>= 1) s += __shfl_xor_sync(0xffffffffu, s, o);
        if (lane == 0) exacts[w][c] = s;
    }
    __syncwarp();

    if (lane == 0) {
        #pragma unroll
        for (int r = 0; r < TOPK; r++) {
            int bj = 0;
            float bvv = exacts[w][0];
            #pragma unroll
            for (int i = 1; i < NCAND; i++) {
                float vi = exacts[w][i];
                if (vi > bvv || (vi == bvv && cands[w][i] < cands[w][bj])) {
                    bvv = vi; bj = i;
                }
            }
            g_topk[b * TOPK + r] = cands[w][bj];
            if (r == 0 && write_assign) {
                #pragma unroll
                for (int dd = 0; dd < D_N; dd++)
                    out[(size_t)B_N * F_N + (size_t)dd * B_N + b] = (float)cands[w][bj];
            }
            exacts[w][bj] = -3.0e38f;
        }
    }
}

// ---------------- aggp (tf32), x0 = tf32(features), am0 = max(aggp,x0) -----
__global__ void aggproto_kernel(const float* __restrict__ graphone,
                                const float* __restrict__ features) {
    int b = blockIdx.x;
    int t = threadIdx.x;
    __shared__ int idx[TOPK];
    if (t < TOPK) idx[t] = g_topk[b * TOPK + t];
    __syncthreads();
    float4 m = ((const float4*)(graphone + (size_t)idx[0] * F_N))[t];
    #pragma unroll
    for (int j = 1; j < TOPK; j++) {
        float4 v = ((const float4*)(graphone + (size_t)idx[j] * F_N))[t];
        m.x = fmaxf(m.x, v.x); m.y = fmaxf(m.y, v.y);
        m.z = fmaxf(m.z, v.z); m.w = fmaxf(m.w, v.w);
    }
    m.x = tf32r(m.x); m.y = tf32r(m.y); m.z = tf32r(m.z); m.w = tf32r(m.w);
    ((float4*)(g_aggp + (size_t)b * F_N))[t] = m;
    float4 f = ((const float4*)(features + (size_t)b * F_N))[t];
    f.x = tf32r(f.x); f.y = tf32r(f.y); f.z = tf32r(f.z); f.w = tf32r(f.w);
    ((float4*)(g_x + (size_t)b * F_N))[t] = f;
    float4 a;
    a.x = fmaxf(m.x, f.x); a.y = fmaxf(m.y, f.y);
    a.z = fmaxf(m.z, f.z); a.w = fmaxf(m.w, f.w);
    ((float4*)(g_am + (size_t)b * F_N))[t] = a;
}

// ---------------- LayerNorm + ReLU + tf32 round, in place on g_h -----------
__global__ void ln_relu_kernel(const float* __restrict__ gamma,
                               const float* __restrict__ beta) {
    int b = blockIdx.x;
    int t = threadIdx.x;
    float* row = g_h + (size_t)b * H_N;
    float4 v = ((float4*)row)[t];
    float s  = v.x + v.y + v.z + v.w;
    float ss = v.x*v.x + v.y*v.y + v.z*v.z + v.w*v.w;
    __shared__ float r1[8], r2[8];
    #pragma unroll
    for (int o = 16; o > 0; o >>= 1) {
        s  += __shfl_xor_sync(0xffffffffu, s,  o);
        ss += __shfl_xor_sync(0xffffffffu, ss, o);
    }
    if ((t & 31) == 0) { r1[t >> 5] = s; r2[t >> 5] = ss; }
    __syncthreads();
    if (t == 0) {
        float a = 0.f, c = 0.f;
        #pragma unroll
        for (int i = 0; i < 8; i++) { a += r1[i]; c += r2[i]; }
        r1[0] = a; r2[0] = c;
    }
    __syncthreads();
    float mu  = r1[0] * (1.0f / H_N);
    float var = r2[0] * (1.0f / H_N) - mu * mu;
    float inv = rsqrtf(var + LN_EPS);
    float4 gm = ((const float4*)gamma)[t];
    float4 be = ((const float4*)beta)[t];
    v.x = tf32r(fmaxf((v.x - mu) * inv * gm.x + be.x, 0.f));
    v.y = tf32r(fmaxf((v.y - mu) * inv * gm.y + be.y, 0.f));
    v.z = tf32r(fmaxf((v.z - mu) * inv * gm.z + be.z, 0.f));
    v.w = tf32r(fmaxf((v.w - mu) * inv * gm.w + be.w, 0.f));
    ((float4*)row)[t] = v;
}

// ---------------------------------------------------------------------------
extern "C" void kernel_launch(void* const* d_in, const int* in_sizes, int n_in,
                              void* d_out, int out_size) {
    const float* features = (const float*)d_in[0];
    const float* graphone = (const float*)d_in[1];
    const float* W_l      = (const float*)d_in[2];
    const float* W_r      = (const float*)d_in[3];
    const float* gamma    = (const float*)d_in[4];
    const float* beta     = (const float*)d_in[5];
    const float* W_p      = (const float*)d_in[6];
    const float* b_p      = (const float*)d_in[7];
    float* out = (float*)d_out;

    float *fnr, *gnr, *sim, *aggp, *x, *h, *am, *wl, *wr, *wp;
    cudaGetSymbolAddress((void**)&fnr,  g_fnr);
    cudaGetSymbolAddress((void**)&gnr,  g_gnr);
    cudaGetSymbolAddress((void**)&sim,  g_sim);
    cudaGetSymbolAddress((void**)&aggp, g_aggp);
    cudaGetSymbolAddress((void**)&x,    g_x);
    cudaGetSymbolAddress((void**)&h,    g_h);
    cudaGetSymbolAddress((void**)&am,   g_am);
    cudaGetSymbolAddress((void**)&wl,   g_wl);
    cudaGetSymbolAddress((void**)&wr,   g_wr);
    cudaGetSymbolAddress((void**)&wp,   g_wp);

    const int GEMM_SMEM = 3 * 128 * 32 * 4 * 2;   // 96 KB (3-stage, A+B)
    const int TOPK_SMEM = 8 * K_N * 4;            // 64 KB
    cudaFuncSetAttribute(tgemm<2, 0>, cudaFuncAttributeMaxDynamicSharedMemorySize, GEMM_SMEM);
    cudaFuncSetAttribute(tgemm<1, 0>, cudaFuncAttributeMaxDynamicSharedMemorySize, GEMM_SMEM);
    cudaFuncSetAttribute(tgemm<2, 1>, cudaFuncAttributeMaxDynamicSharedMemorySize, GEMM_SMEM);
    cudaFuncSetAttribute(tgemm<2, 2>, cudaFuncAttributeMaxDynamicSharedMemorySize, GEMM_SMEM);
    cudaFuncSetAttribute(topk_kernel, cudaFuncAttributeMaxDynamicSharedMemorySize, TOPK_SMEM);

    // 0+1) fused: row normalization + weight tf32 rounding (one launch)
    prep_kernel<<<NPREP + NCONV, 256>>>(features, graphone, W_l, W_r, W_p);

    // 2) APPROX sim = fnr @ gnr^T  (plain TF32 TC GEMM)
    tgemm<2, 0><<<dim3(K_N / 128, B_N / 128), 256, GEMM_SMEM>>>(
        fnr, nullptr, gnr, nullptr, nullptr, nullptr, sim, nullptr,
        B_N, K_N, F_N);

    // 3) warp-private top-16 -> exact rescore -> top-8 (+ assignments)
    long long need = (long long)B_N * F_N + (long long)D_N * B_N;
    int write_assign = ((long long)out_size >= need) ? 1 : 0;
    topk_kernel<<<B_N / 8, 256, TOPK_SMEM>>>(out, write_assign);

    // 4) aggp (tf32), x0 = tf32(features), am0 = max(aggp, x0)
    aggproto_kernel<<<B_N, 256>>>(graphone, features);

    // 5) depth loop — tensor-core TF32 GEMMs
    for (int d = 0; d < D_N; d++) {
        tgemm<1, 0><<<dim3(H_N / 128, B_N / 128), 256, GEMM_SMEM>>>(
            am, x,
            wl + (size_t)d * H_N * F_N, wr + (size_t)d * H_N * F_N,
            nullptr, nullptr, h, nullptr, B_N, H_N, 2 * F_N);

        ln_relu_kernel<<<B_N, 256>>>(gamma + (size_t)d * H_N,
                                     beta  + (size_t)d * H_N);

        if (d < D_N - 1) {
            tgemm<2, 1><<<dim3(F_N / 128, B_N / 128), 256, GEMM_SMEM>>>(
                h, nullptr, wp + (size_t)d * F_N * H_N, nullptr,
                b_p + (size_t)d * F_N, aggp, x, am, B_N, F_N, H_N);
        } else {
            tgemm<2, 2><<<dim3(F_N / 128, B_N / 128), 256, GEMM_SMEM>>>(
                h, nullptr, wp + (size_t)d * F_N * H_N, nullptr,
                b_p + (size_t)d * F_N, nullptr, out, nullptr, B_N, F_N, H_N);
        }
    }
}

// round 17
// speedup vs baseline: 1.1999x; 1.0055x over previous
#include <cuda_runtime.h>
#include <cstdint>

#define B_N   16384
#define K_N   2048
#define F_N   1024
#define H_N   1024
#define D_N   3
#define TOPK  8
#define NCAND 16
#define LN_EPS 1e-5f

// ---------------- scratch (static device globals; no runtime allocation) ---
__device__ float g_fn  [(size_t)B_N * F_N];   // normalized features (fp32, exact)
__device__ float g_gn  [(size_t)K_N * F_N];   // normalized graphone (fp32, exact)
__device__ float g_fnr [(size_t)B_N * F_N];   // tf32-rounded fn (for approx sim)
__device__ float g_gnr [(size_t)K_N * F_N];   // tf32-rounded gn
__device__ float g_sim [(size_t)B_N * K_N];   // APPROX similarity (1xTF32)
__device__ int   g_topk[(size_t)B_N * TOPK];  // top-8 prototype idx per row
__device__ float g_aggp[(size_t)B_N * F_N];   // max over top-8 graphone rows (tf32)
__device__ float g_x   [(size_t)B_N * F_N];   // depth-loop activations (tf32)
__device__ float g_am  [(size_t)B_N * F_N];   // max(aggp, x) (tf32)
__device__ float g_h   [(size_t)B_N * H_N];   // hidden
__device__ float g_wl  [(size_t)D_N * H_N * F_N];  // tf32-rounded weights
__device__ float g_wr  [(size_t)D_N * H_N * F_N];
__device__ float g_wp  [(size_t)D_N * F_N * H_N];

// ---------------- small PTX helpers ----------------------------------------
__device__ __forceinline__ float tf32r(float x) {
    float r;
    asm("cvt.rna.tf32.f32 %0, %1;" : "=f"(r) : "f"(x));
    return r;
}
__device__ __forceinline__ void ldsm4(uint32_t& r0, uint32_t& r1,
                                      uint32_t& r2, uint32_t& r3, uint32_t a) {
    asm volatile("ldmatrix.sync.aligned.m8n8.x4.shared.b16 {%0,%1,%2,%3}, [%4];"
                 : "=r"(r0), "=r"(r1), "=r"(r2), "=r"(r3) : "r"(a));
}
__device__ __forceinline__ void mma_tf32(float c[4],
                                         uint32_t a0, uint32_t a1, uint32_t a2, uint32_t a3,
                                         uint32_t b0, uint32_t b1) {
    asm volatile("mma.sync.aligned.m16n8k8.row.col.f32.tf32.tf32.f32 "
                 "{%0,%1,%2,%3},{%4,%5,%6,%7},{%8,%9},{%0,%1,%2,%3};"
                 : "+f"(c[0]), "+f"(c[1]), "+f"(c[2]), "+f"(c[3])
                 : "r"(a0), "r"(a1), "r"(a2), "r"(a3), "r"(b0), "r"(b1));
}
__device__ __forceinline__ void cpasync16(uint32_t dst, const void* src) {
    asm volatile("cp.async.cg.shared.global [%0], [%1], 16;" :: "r"(dst), "l"(src));
}
__device__ __forceinline__ void cp_commit() {
    asm volatile("cp.async.commit_group;");
}
__device__ __forceinline__ void cp_wait0() {
    asm volatile("cp.async.wait_group 0;");
}
__device__ __forceinline__ void cp_wait1() {
    asm volatile("cp.async.wait_group 1;");
}

// ---------------- fused prep: row L2 normalize + weight tf32 rounding ------
// Blocks [0, B_N+K_N): normalize one row (exact + tf32-rounded copies).
// Blocks [B_N+K_N, B_N+K_N+NCONV): tf32-round the three weight tensors.
#define NPREP (B_N + K_N)
#define NW4   (D_N * H_N * F_N / 4)              // float4s per weight tensor
#define NCONV ((3 * NW4 + 255) / 256)

__global__ void prep_kernel(const float* __restrict__ feat,
                            const float* __restrict__ gr,
                            const float* __restrict__ W_l,
                            const float* __restrict__ W_r,
                            const float* __restrict__ W_p) {
    int blk = blockIdx.x;
    int t = threadIdx.x;
    if (blk >= NPREP) {
        int i = (blk - NPREP) * 256 + t;
        if (i >= 3 * NW4) return;
        const float* src; float* dst; int j;
        if (i < NW4)            { src = W_l; dst = g_wl; j = i; }
        else if (i < 2 * NW4)   { src = W_r; dst = g_wr; j = i - NW4; }
        else                    { src = W_p; dst = g_wp; j = i - 2 * NW4; }
        float4 v = ((const float4*)src)[j];
        v.x = tf32r(v.x); v.y = tf32r(v.y); v.z = tf32r(v.z); v.w = tf32r(v.w);
        ((float4*)dst)[j] = v;
        return;
    }
    int row = blk;
    const float* src;
    float* dst; float* dstr;
    if (row < B_N) {
        src = feat + (size_t)row * F_N;
        dst = g_fn + (size_t)row * F_N;  dstr = g_fnr + (size_t)row * F_N;
    } else {
        row -= B_N;
        src = gr + (size_t)row * F_N;
        dst = g_gn + (size_t)row * F_N;  dstr = g_gnr + (size_t)row * F_N;
    }
    float4 v = ((const float4*)src)[t];
    float ss = v.x*v.x + v.y*v.y + v.z*v.z + v.w*v.w;
    __shared__ float red[8];
    #pragma unroll
    for (int o = 16; o > 0; o >>= 1) ss += __shfl_xor_sync(0xffffffffu, ss, o);
    if ((t & 31) == 0) red[t >> 5] = ss;
    __syncthreads();
    if (t == 0) {
        float s = 0.f;
        #pragma unroll
        for (int i = 0; i < 8; i++) s += red[i];
        red[0] = s;
    }
    __syncthreads();
    float inv = rsqrtf(red[0]);
    v.x *= inv; v.y *= inv; v.z *= inv; v.w *= inv;
    ((float4*)dst)[t] = v;
    float4 r4;
    r4.x = tf32r(v.x); r4.y = tf32r(v.y); r4.z = tf32r(v.z); r4.w = tf32r(v.w);
    ((float4*)dstr)[t] = r4;
}

// ---------------- TF32 tensor-core NT GEMM, BK=32, 3-stage, dyn smem -------
// (round-12 winner, byte-identical numerics)
// MODE 1: dual phase (Kd = 2F): k<F uses (A0,B0), k>=F uses (A1,B1), lda=F
// MODE 2: single (A0,B0)
// EPI 0: store raw   EPI 1: +bias,tf32,Am=max(aggp,x)   EPI 2: +bias -> out
template <int MODE, int EPI>
__global__ void __launch_bounds__(256, 2)
tgemm(const float* __restrict__ A0, const float* __restrict__ A1,
      const float* __restrict__ B0p, const float* __restrict__ B1p,
      const float* __restrict__ bias, const float* __restrict__ aggp,
      float* __restrict__ C, float* __restrict__ Am,
      int M, int N, int Kd) {
    const int BM = 128, BK = 32, NS = 3;
    const int STG = BM * BK;
    extern __shared__ float smem[];
    float* As = smem;                         // NS*STG floats (48 KB)
    float* Bs = smem + NS * STG;              // NS*STG floats (48 KB)

    const int tid  = threadIdx.x;
    const int lane = tid & 31;
    const int warp = tid >> 5;
    const int wm = warp >> 2;
    const int wn = warp & 3;
    const int g  = lane >> 3;
    const int li = lane & 7;
    const int m0 = blockIdx.y * BM;
    const int n0 = blockIdx.x * BM;

    const uint32_t sA = (uint32_t)__cvta_generic_to_shared(As);
    const uint32_t sB = (uint32_t)__cvta_generic_to_shared(Bs);

    float acc[4][4][4];
    #pragma unroll
    for (int a = 0; a < 4; a++)
        #pragma unroll
        for (int b = 0; b < 4; b++)
            #pragma unroll
            for (int c = 0; c < 4; c++) acc[a][b][c] = 0.f;

    const int halfK = Kd >> 1;
    const int NT = Kd / BK;

    // SW128 swizzle over 8 16B-chunks per 128B row: chunk' = c8 ^ (row & 7)
    auto issue_loads = [&](int kt) {
        int kk = kt * BK;
        int buf = kt % NS;
        const float* Aptr; const float* Bptr; int kb = kk; int ld;
        if (MODE == 1) {
            ld = halfK;
            if (kk >= halfK) { Aptr = A1; Bptr = B1p; kb = kk - halfK; }
            else             { Aptr = A0; Bptr = B0p; }
        } else {
            ld = Kd; Aptr = A0; Bptr = B0p;
        }
        #pragma unroll
        for (int it = 0; it < 4; it++) {      // 1024 float4 per operand
            int f = tid + it * 256;
            int r = f >> 3, c8 = f & 7;
            uint32_t soff = (uint32_t)(buf * STG + r * BK + ((c8 ^ (r & 7)) << 2)) * 4u;
            cpasync16(sA + soff, Aptr + (size_t)(m0 + r) * ld + kb + c8 * 4);
            cpasync16(sB + soff, Bptr + (size_t)(n0 + r) * ld + kb + c8 * 4);
        }
        cp_commit();
    };

    issue_loads(0);
    issue_loads(1);

    for (int kt = 0; kt < NT; kt++) {
        if (kt + 1 < NT) cp_wait1(); else cp_wait0();
        __syncthreads();
        if (kt + 2 < NT) issue_loads(kt + 2);

        const uint32_t baseA = sA + (uint32_t)((kt % NS) * STG) * 4u;
        const uint32_t baseB = sB + (uint32_t)((kt % NS) * STG) * 4u;

        #pragma unroll
        for (int s = 0; s < 4; s++) {         // 4 k=8 slices per BK=32
            uint32_t a[4][4];
            #pragma unroll
            for (int mi = 0; mi < 4; mi++) {
                int row = wm * 64 + mi * 16 + ((g & 1) << 3) + li;
                int ch  = (2 * s + (g >> 1)) ^ (row & 7);
                ldsm4(a[mi][0], a[mi][1], a[mi][2], a[mi][3],
                      baseA + (uint32_t)((row * BK + (ch << 2)) << 2));
            }
            uint32_t b[4][2];
            #pragma unroll
            for (int p = 0; p < 2; p++) {
                int row = wn * 32 + p * 16 + ((g >> 1) << 3) + li;
                int ch  = (2 * s + (g & 1)) ^ (row & 7);
                uint32_t r0, r1, r2, r3;
                ldsm4(r0, r1, r2, r3,
                      baseB + (uint32_t)((row * BK + (ch << 2)) << 2));
                b[2*p][0] = r0; b[2*p][1] = r1;
                b[2*p+1][0] = r2; b[2*p+1][1] = r3;
            }
            #pragma unroll
            for (int mi = 0; mi < 4; mi++)
                #pragma unroll
                for (int nj = 0; nj < 4; nj++)
                    mma_tf32(acc[mi][nj], a[mi][0], a[mi][1], a[mi][2], a[mi][3],
                             b[nj][0], b[nj][1]);
        }
    }

    #pragma unroll
    for (int mi = 0; mi < 4; mi++) {
        #pragma unroll
        for (int half = 0; half < 2; half++) {
            int row = m0 + wm * 64 + mi * 16 + (lane >> 2) + half * 8;
            #pragma unroll
            for (int nj = 0; nj < 4; nj++) {
                int col = n0 + wn * 32 + nj * 8 + ((lane & 3) << 1);
                float v0 = acc[mi][nj][half * 2 + 0];
                float v1 = acc[mi][nj][half * 2 + 1];
                size_t idx = (size_t)row * N + col;
                if (EPI >= 1) {
                    float2 bb = *(const float2*)(bias + col);
                    v0 += bb.x; v1 += bb.y;
                }
                if (EPI == 1) {
                    v0 = tf32r(v0); v1 = tf32r(v1);
                    float2 ag = *(const float2*)(aggp + idx);
                    float2 am;
                    am.x = fmaxf(ag.x, v0); am.y = fmaxf(ag.y, v1);
                    *(float2*)(Am + idx) = am;
                }
                float2 vv; vv.x = v0; vv.y = v1;
                *(float2*)(C + idx) = vv;
            }
        }
    }
}

// ---------------- warp-private topk (round-9/12 winner, unchanged) ----------
__global__ void __launch_bounds__(256)
topk_kernel(float* __restrict__ out, int write_assign) {
    extern __shared__ float svall[];          // 8 * 2048 floats = 64 KB
    int t = threadIdx.x;
    int lane = t & 31, w = t >> 5;
    int b = blockIdx.x * 8 + w;
    float* svw = svall + w * K_N;

    __shared__ int   cands[8][NCAND];
    __shared__ float exacts[8][NCAND];

    const float* row = g_sim + (size_t)b * K_N;
    float lmax = -3.0e38f; int lidx = 0;
    #pragma unroll
    for (int e = 0; e < 16; e++) {
        int q = lane + e * 32;
        float4 v = ((const float4*)row)[q];
        ((float4*)svw)[q] = v;
        int i0 = q * 4;
        if (v.x > lmax) { lmax = v.x; lidx = i0; }
        if (v.y > lmax) { lmax = v.y; lidx = i0 + 1; }
        if (v.z > lmax) { lmax = v.z; lidx = i0 + 2; }
        if (v.w > lmax) { lmax = v.w; lidx = i0 + 3; }
    }
    __syncwarp();

    for (int r = 0; r < NCAND; r++) {
        float bv = lmax; int bi = lidx;
        #pragma unroll
        for (int o = 16; o > 0; o >>= 1) {
            float ov = __shfl_xor_sync(0xffffffffu, bv, o);
            int   oi = __shfl_xor_sync(0xffffffffu, bi, o);
            if (ov > bv || (ov == bv && oi < bi)) { bv = ov; bi = oi; }
        }
        if (lane == 0) cands[w][r] = bi;
        if (((bi >> 2) & 31) == lane) {
            svw[bi] = -3.0e38f;
            lmax = -3.0e38f; lidx = 0;
            #pragma unroll
            for (int e = 0; e < 16; e++) {
                int q = lane + e * 32;
                float4 v = ((const float4*)svw)[q];
                int i0 = q * 4;
                if (v.x > lmax) { lmax = v.x; lidx = i0; }
                if (v.y > lmax) { lmax = v.y; lidx = i0 + 1; }
                if (v.z > lmax) { lmax = v.z; lidx = i0 + 2; }
                if (v.w > lmax) { lmax = v.w; lidx = i0 + 3; }
            }
        }
        __syncwarp();
    }

    const float* fp = g_fn + (size_t)b * F_N;
    for (int c = 0; c < NCAND; c++) {
        const float* gp = g_gn + (size_t)cands[w][c] * F_N;
        float s = 0.f;
        #pragma unroll
        for (int e = 0; e < F_N / 32; e++)
            s = fmaf(fp[e * 32 + lane], gp[e * 32 + lane], s);
        #pragma unroll
        for (int o = 16; o > 0; o >>= 1) s += __shfl_xor_sync(0xffffffffu, s, o);
        if (lane == 0) exacts[w][c] = s;
    }
    __syncwarp();

    if (lane == 0) {
        #pragma unroll
        for (int r = 0; r < TOPK; r++) {
            int bj = 0;
            float bvv = exacts[w][0];
            #pragma unroll
            for (int i = 1; i < NCAND; i++) {
                float vi = exacts[w][i];
                if (vi > bvv || (vi == bvv && cands[w][i] < cands[w][bj])) {
                    bvv = vi; bj = i;
                }
            }
            g_topk[b * TOPK + r] = cands[w][bj];
            if (r == 0 && write_assign) {
                #pragma unroll
                for (int dd = 0; dd < D_N; dd++)
                    out[(size_t)B_N * F_N + (size_t)dd * B_N + b] = (float)cands[w][bj];
            }
            exacts[w][bj] = -3.0e38f;
        }
    }
}

// ---------------- aggp (tf32), x0 = tf32(features), am0 = max(aggp,x0) -----
__global__ void aggproto_kernel(const float* __restrict__ graphone,
                                const float* __restrict__ features) {
    int b = blockIdx.x;
    int t = threadIdx.x;
    __shared__ int idx[TOPK];
    if (t < TOPK) idx[t] = g_topk[b * TOPK + t];
    __syncthreads();
    float4 m = ((const float4*)(graphone + (size_t)idx[0] * F_N))[t];
    #pragma unroll
    for (int j = 1; j < TOPK; j++) {
        float4 v = ((const float4*)(graphone + (size_t)idx[j] * F_N))[t];
        m.x = fmaxf(m.x, v.x); m.y = fmaxf(m.y, v.y);
        m.z = fmaxf(m.z, v.z); m.w = fmaxf(m.w, v.w);
    }
    m.x = tf32r(m.x); m.y = tf32r(m.y); m.z = tf32r(m.z); m.w = tf32r(m.w);
    ((float4*)(g_aggp + (size_t)b * F_N))[t] = m;
    float4 f = ((const float4*)(features + (size_t)b * F_N))[t];
    f.x = tf32r(f.x); f.y = tf32r(f.y); f.z = tf32r(f.z); f.w = tf32r(f.w);
    ((float4*)(g_x + (size_t)b * F_N))[t] = f;
    float4 a;
    a.x = fmaxf(m.x, f.x); a.y = fmaxf(m.y, f.y);
    a.z = fmaxf(m.z, f.z); a.w = fmaxf(m.w, f.w);
    ((float4*)(g_am + (size_t)b * F_N))[t] = a;
}

// ---------------- LayerNorm + ReLU + tf32 round: 2 rows per block ----------
// 256 threads = 2 groups of 128 (4 warps each); one row per group, arithmetic
// identical to the 1-row version (same sum order: 4-elem local, warp shfl,
// 4-partial combine).
__global__ void ln_relu_kernel(const float* __restrict__ gamma,
                               const float* __restrict__ beta) {
    int t = threadIdx.x;
    int grp = t >> 7;                         // 0..1 (row within block)
    int gt  = t & 127;                        // thread within group
    int b = blockIdx.x * 2 + grp;
    float* row = g_h + (size_t)b * H_N;
    __shared__ float r1[2][4], r2[2][4], bc[2][2];

    float4 v0 = ((float4*)row)[gt];
    float4 v1 = ((float4*)row)[gt + 128];
    float s  = v0.x + v0.y + v0.z + v0.w + v1.x + v1.y + v1.z + v1.w;
    float ss = v0.x*v0.x + v0.y*v0.y + v0.z*v0.z + v0.w*v0.w
             + v1.x*v1.x + v1.y*v1.y + v1.z*v1.z + v1.w*v1.w;
    #pragma unroll
    for (int o = 16; o > 0; o >>= 1) {
        s  += __shfl_xor_sync(0xffffffffu, s,  o);
        ss += __shfl_xor_sync(0xffffffffu, ss, o);
    }
    if ((gt & 31) == 0) { r1[grp][gt >> 5] = s; r2[grp][gt >> 5] = ss; }
    __syncthreads();
    if (gt == 0) {
        float a = 0.f, c = 0.f;
        #pragma unroll
        for (int i = 0; i < 4; i++) { a += r1[grp][i]; c += r2[grp][i]; }
        bc[grp][0] = a; bc[grp][1] = c;
    }
    __syncthreads();
    float mu  = bc[grp][0] * (1.0f / H_N);
    float var = bc[grp][1] * (1.0f / H_N) - mu * mu;
    float inv = rsqrtf(var + LN_EPS);

    float4 gm0 = ((const float4*)gamma)[gt];
    float4 be0 = ((const float4*)beta)[gt];
    v0.x = tf32r(fmaxf((v0.x - mu) * inv * gm0.x + be0.x, 0.f));
    v0.y = tf32r(fmaxf((v0.y - mu) * inv * gm0.y + be0.y, 0.f));
    v0.z = tf32r(fmaxf((v0.z - mu) * inv * gm0.z + be0.z, 0.f));
    v0.w = tf32r(fmaxf((v0.w - mu) * inv * gm0.w + be0.w, 0.f));
    ((float4*)row)[gt] = v0;
    float4 gm1 = ((const float4*)gamma)[gt + 128];
    float4 be1 = ((const float4*)beta)[gt + 128];
    v1.x = tf32r(fmaxf((v1.x - mu) * inv * gm1.x + be1.x, 0.f));
    v1.y = tf32r(fmaxf((v1.y - mu) * inv * gm1.y + be1.y, 0.f));
    v1.z = tf32r(fmaxf((v1.z - mu) * inv * gm1.z + be1.z, 0.f));
    v1.w = tf32r(fmaxf((v1.w - mu) * inv * gm1.w + be1.w, 0.f));
    ((float4*)row)[gt + 128] = v1;
}

// ---------------------------------------------------------------------------
extern "C" void kernel_launch(void* const* d_in, const int* in_sizes, int n_in,
                              void* d_out, int out_size) {
    const float* features = (const float*)d_in[0];
    const float* graphone = (const float*)d_in[1];
    const float* W_l      = (const float*)d_in[2];
    const float* W_r      = (const float*)d_in[3];
    const float* gamma    = (const float*)d_in[4];
    const float* beta     = (const float*)d_in[5];
    const float* W_p      = (const float*)d_in[6];
    const float* b_p      = (const float*)d_in[7];
    float* out = (float*)d_out;

    float *fnr, *gnr, *sim, *aggp, *x, *h, *am, *wl, *wr, *wp;
    cudaGetSymbolAddress((void**)&fnr,  g_fnr);
    cudaGetSymbolAddress((void**)&gnr,  g_gnr);
    cudaGetSymbolAddress((void**)&sim,  g_sim);
    cudaGetSymbolAddress((void**)&aggp, g_aggp);
    cudaGetSymbolAddress((void**)&x,    g_x);
    cudaGetSymbolAddress((void**)&h,    g_h);
    cudaGetSymbolAddress((void**)&am,   g_am);
    cudaGetSymbolAddress((void**)&wl,   g_wl);
    cudaGetSymbolAddress((void**)&wr,   g_wr);
    cudaGetSymbolAddress((void**)&wp,   g_wp);

    const int GEMM_SMEM = 3 * 128 * 32 * 4 * 2;   // 96 KB (3-stage, A+B)
    const int TOPK_SMEM = 8 * K_N * 4;            // 64 KB
    cudaFuncSetAttribute(tgemm<2, 0>, cudaFuncAttributeMaxDynamicSharedMemorySize, GEMM_SMEM);
    cudaFuncSetAttribute(tgemm<1, 0>, cudaFuncAttributeMaxDynamicSharedMemorySize, GEMM_SMEM);
    cudaFuncSetAttribute(tgemm<2, 1>, cudaFuncAttributeMaxDynamicSharedMemorySize, GEMM_SMEM);
    cudaFuncSetAttribute(tgemm<2, 2>, cudaFuncAttributeMaxDynamicSharedMemorySize, GEMM_SMEM);
    cudaFuncSetAttribute(topk_kernel, cudaFuncAttributeMaxDynamicSharedMemorySize, TOPK_SMEM);

    // 0+1) fused: row normalization + weight tf32 rounding (one launch)
    prep_kernel<<<NPREP + NCONV, 256>>>(features, graphone, W_l, W_r, W_p);

    // 2) APPROX sim = fnr @ gnr^T  (plain TF32 TC GEMM)
    tgemm<2, 0><<<dim3(K_N / 128, B_N / 128), 256, GEMM_SMEM>>>(
        fnr, nullptr, gnr, nullptr, nullptr, nullptr, sim, nullptr,
        B_N, K_N, F_N);

    // 3) warp-private top-16 -> exact rescore -> top-8 (+ assignments)
    long long need = (long long)B_N * F_N + (long long)D_N * B_N;
    int write_assign = ((long long)out_size >= need) ? 1 : 0;
    topk_kernel<<<B_N / 8, 256, TOPK_SMEM>>>(out, write_assign);

    // 4) aggp (tf32), x0 = tf32(features), am0 = max(aggp, x0)
    aggproto_kernel<<<B_N, 256>>>(graphone, features);

    // 5) depth loop — tensor-core TF32 GEMMs
    for (int d = 0; d < D_N; d++) {
        tgemm<1, 0><<<dim3(H_N / 128, B_N / 128), 256, GEMM_SMEM>>>(
            am, x,
            wl + (size_t)d * H_N * F_N, wr + (size_t)d * H_N * F_N,
            nullptr, nullptr, h, nullptr, B_N, H_N, 2 * F_N);

        ln_relu_kernel<<<B_N / 2, 256>>>(gamma + (size_t)d * H_N,
                                         beta  + (size_t)d * H_N);

        if (d < D_N - 1) {
            tgemm<2, 1><<<dim3(F_N / 128, B_N / 128), 256, GEMM_SMEM>>>(
                h, nullptr, wp + (size_t)d * F_N * H_N, nullptr,
                b_p + (size_t)d * F_N, aggp, x, am, B_N, F_N, H_N);
        } else {
            tgemm<2, 2><<<dim3(F_N / 128, B_N / 128), 256, GEMM_SMEM>>>(
                h, nullptr, wp + (size_t)d * F_N * H_N, nullptr,
                b_p + (size_t)d * F_N, nullptr, out, nullptr, B_N, F_N, H_N);
        }
    }
}